// round 1
// baseline (speedup 1.0000x reference)
#include <cuda_runtime.h>
#include <math.h>

#define FULL 0xffffffffu

// Precomputed cos/sin of half-angles for the 4 entangler weight sets.
// [ci*10 + w] = (cos(w_ci[w]/2), sin(w_ci[w]/2))
__device__ float2 g_cs[40];

__global__ void setup_kernel(const float* __restrict__ wf,
                             const float* __restrict__ wi,
                             const float* __restrict__ wu,
                             const float* __restrict__ wo) {
    int t = threadIdx.x;
    if (t < 40) {
        int ci = t / 10, w = t % 10;
        const float* p = (ci == 0) ? wf : (ci == 1) ? wi : (ci == 2) ? wu : wo;
        float s, c;
        sincosf(0.5f * p[w], &s, &c);
        g_cs[t] = make_float2(c, s);
    }
}

// One warp per batch row. State: 1024 complex amps -> 32 complex per lane.
// Amp index k: bits [9:5] = lane id, bits [4:0] = local register index.
// Wire w <-> bit position p = 9 - w (PennyLane MSB-first convention).
__global__ void __launch_bounds__(128)
qlstm_kernel(const float* __restrict__ x, const float* __restrict__ W,
             const float* __restrict__ b, float* __restrict__ out) {
    const int warp = (blockIdx.x * blockDim.x + threadIdx.x) >> 5;
    const int lane = threadIdx.x & 31;

    // ---------------- h = x[warp] @ W^T + b (butterfly-reduced) --------------
    const float4 xv = reinterpret_cast<const float4*>(x + (size_t)warp * 128)[lane];
    float h[10];
#pragma unroll
    for (int o = 0; o < 10; o++) {
        const float4 wv = reinterpret_cast<const float4*>(W + o * 128)[lane];
        float acc = xv.x * wv.x + xv.y * wv.y + xv.z * wv.z + xv.w * wv.w;
#pragma unroll
        for (int s = 16; s; s >>= 1) acc += __shfl_xor_sync(FULL, acc, s);
        h[o] = acc + __ldg(b + o);
    }

    // Per-lane angle: lane q computes sincos(h_q/2); broadcast all 10.
    float my_h = h[0];
#pragma unroll
    for (int o = 1; o < 10; o++)
        if (lane == o) my_h = h[o];
    float msn, mcs;
    sincosf(0.5f * my_h, &msn, &mcs);
    float cw[10], sw[10];
#pragma unroll
    for (int w = 0; w < 10; w++) {
        cw[w] = __shfl_sync(FULL, mcs, w);
        sw[w] = __shfl_sync(FULL, msn, w);
    }

    // ------------- product-state magnitudes m[k] (real, signed) -------------
    // lane bit j -> amp bit 5+j -> wire 4-j ; local bit j -> amp bit j -> wire 9-j
    float prefix = 1.0f;
#pragma unroll
    for (int j = 0; j < 5; j++)
        prefix *= ((lane >> j) & 1) ? sw[4 - j] : cw[4 - j];

    float m[32];
    m[0] = prefix;
#pragma unroll
    for (int j = 0; j < 5; j++) {
        const int wq = 9 - j;
#pragma unroll
        for (int i = 0; i < (1 << j); i++) {
            m[i | (1 << j)] = m[i] * sw[wq];
            m[i]            = m[i] * cw[wq];
        }
    }

    // Phase (-i)^popc(k): class tables for popc(local)&3, offset by popc(lane).
    const int pb = __popc(lane) & 3;
    float rc[4], ic[4];
#pragma unroll
    for (int t = 0; t < 4; t++) {
        int ph = (pb + t) & 3;
        rc[t] = (ph == 0) ? 1.0f : (ph == 2) ? -1.0f : 0.0f;
        ic[t] = (ph == 1) ? -1.0f : (ph == 3) ? 1.0f : 0.0f;
    }

    float e0 = 0.f, e1 = 0.f, e2 = 0.f, e3 = 0.f;

    for (int ci = 0; ci < 4; ci++) {
        // entangler rotation coefficients (warp-uniform, L2-resident)
        float gc[10], gs[10];
#pragma unroll
        for (int w = 0; w < 10; w++) {
            float2 t = g_cs[ci * 10 + w];
            gc[w] = t.x; gs[w] = t.y;
        }
        const bool ry = (ci == 1);  // w_input circuit uses RY

        // -------- materialize psi0 --------
        float re[32], im[32];
#pragma unroll
        for (int i = 0; i < 32; i++) {
            const int t = __popc(i) & 3;  // compile-time
            re[i] = m[i] * rc[t];
            im[i] = m[i] * ic[t];
        }

        // -------- rotations on wires 0..4 (lane bits, j = 4-w) --------
#pragma unroll
        for (int w = 0; w < 5; w++) {
            const float c = gc[w], s = gs[w];
            const int j = 4 - w;
            const float se = ((lane >> j) & 1) ? s : -s;  // RY sign
#pragma unroll
            for (int i = 0; i < 32; i++) {
                float pre = __shfl_xor_sync(FULL, re[i], 1 << j);
                float pim = __shfl_xor_sync(FULL, im[i], 1 << j);
                if (ry) {
                    re[i] = c * re[i] + se * pre;
                    im[i] = c * im[i] + se * pim;
                } else {  // RX: new = c*a + (-i s)*partner
                    re[i] = c * re[i] + s * pim;
                    im[i] = c * im[i] - s * pre;
                }
            }
        }

        // -------- rotations on wires 5..9 (local bits, b = 9-w) --------
#pragma unroll
        for (int w = 5; w < 10; w++) {
            const float c = gc[w], s = gs[w];
            const int bb = 1 << (9 - w);
#pragma unroll
            for (int i = 0; i < 32; i++) {
                if (i & bb) continue;
                const int i1 = i | bb;
                float r0 = re[i], q0 = im[i], r1 = re[i1], q1 = im[i1];
                if (ry) {
                    re[i]  = c * r0 - s * r1;  im[i]  = c * q0 - s * q1;
                    re[i1] = s * r0 + c * r1;  im[i1] = s * q0 + c * q1;
                } else {
                    re[i]  = c * r0 + s * q1;  im[i]  = c * q0 - s * r1;
                    re[i1] = c * r1 + s * q0;  im[i1] = c * q1 - s * r0;
                }
            }
        }

        // -------- CNOT ring (c,t) = (0,1)..(9,0), bit p = 9-wire --------
        // (0,1)..(3,4): both bits are lane bits: control cj, target tj.
#pragma unroll
        for (int g = 0; g < 4; g++) {
            const int cj = 4 - g;      // control lane bit
            const int tj = 3 - g;      // target lane bit
            const bool flip = (lane >> cj) & 1;
#pragma unroll
            for (int i = 0; i < 32; i++) {
                float tr = __shfl_xor_sync(FULL, re[i], 1 << tj);
                float ti = __shfl_xor_sync(FULL, im[i], 1 << tj);
                if (flip) { re[i] = tr; im[i] = ti; }
            }
        }
        // (4,5): control lane bit 0, target local bit 4 -> predicated local swap
        {
            const bool flip = lane & 1;
#pragma unroll
            for (int i = 0; i < 16; i++) {
                const int i1 = i | 16;
                float r0 = re[i], r1 = re[i1], q0 = im[i], q1 = im[i1];
                re[i]  = flip ? r1 : r0;  re[i1] = flip ? r0 : r1;
                im[i]  = flip ? q1 : q0;  im[i1] = flip ? q0 : q1;
            }
        }
        // (5,6)..(8,9): both local -> compile-time register permutation (free)
#pragma unroll
        for (int g = 0; g < 4; g++) {
            const int cb = 4 - g, tb = 3 - g;
#pragma unroll
            for (int i = 0; i < 32; i++) {
                if (((i >> cb) & 1) && !((i >> tb) & 1)) {
                    const int i1 = i | (1 << tb);
                    float t = re[i]; re[i] = re[i1]; re[i1] = t;
                    t = im[i]; im[i] = im[i1]; im[i1] = t;
                }
            }
        }
        // (9,0): control local bit 0, target lane bit 4 -> swap across lane^16
#pragma unroll
        for (int i = 0; i < 32; i++) {
            if (i & 1) {
                re[i] = __shfl_xor_sync(FULL, re[i], 16);
                im[i] = __shfl_xor_sync(FULL, im[i], 16);
            }
        }

        // -------- PauliZ expvals --------
        float p[32];
#pragma unroll
        for (int i = 0; i < 32; i++) p[i] = re[i] * re[i] + im[i] * im[i];

        float S = 0.f;
#pragma unroll
        for (int i = 0; i < 32; i++) S += p[i];

        float v[10];
#pragma unroll
        for (int w = 0; w < 5; w++) {       // lane-bit wires, j = 4-w
            const int j = 4 - w;
            float t = ((lane >> j) & 1) ? -S : S;
#pragma unroll
            for (int s2 = 16; s2; s2 >>= 1) t += __shfl_xor_sync(FULL, t, s2);
            v[w] = t;
        }
#pragma unroll
        for (int w = 5; w < 10; w++) {      // local-bit wires, bl = 9-w
            const int bl = 9 - w;
            float t = 0.f;
#pragma unroll
            for (int i = 0; i < 32; i++) t += ((i >> bl) & 1) ? -p[i] : p[i];
#pragma unroll
            for (int s2 = 16; s2; s2 >>= 1) t += __shfl_xor_sync(FULL, t, s2);
            v[w] = t;
        }

        float mye = v[0];
#pragma unroll
        for (int w = 1; w < 10; w++)
            if (lane == w) mye = v[w];

        if (ci == 0) e0 = mye;
        else if (ci == 1) e1 = mye;
        else if (ci == 2) e2 = mye;
        else e3 = mye;
    }

    // ---------------- LSTM combine (lanes 0..9 hold their wire) -------------
    if (lane < 10) {
        float ing = 1.0f / (1.0f + expf(-e0));   // sigmoid(vqc RX w_forget)
        float fg  = 1.0f / (1.0f + expf(-e1));   // sigmoid(vqc RY w_input)
        float cg  = tanhf(e2);                   // tanh(vqc RX w_update)
        float og  = 1.0f / (1.0f + expf(-e3));   // sigmoid(vqc RX w_output)
        float nh  = my_h * fg + ing * cg;
        out[warp * 10 + lane] = og * tanhf(nh);
    }
}

extern "C" void kernel_launch(void* const* d_in, const int* in_sizes, int n_in,
                              void* d_out, int out_size) {
    const float* x  = (const float*)d_in[0];
    const float* W  = (const float*)d_in[1];
    const float* b  = (const float*)d_in[2];
    const float* wf = (const float*)d_in[3];
    const float* wi = (const float*)d_in[4];
    const float* wu = (const float*)d_in[5];
    const float* wo = (const float*)d_in[6];
    float* out = (float*)d_out;

    setup_kernel<<<1, 64>>>(wf, wi, wu, wo);
    // 16384 rows, one warp each: 4096 blocks x 128 threads
    qlstm_kernel<<<4096, 128>>>(x, W, b, out);
}

// round 2
// speedup vs baseline: 1.2558x; 1.2558x over previous
#include <cuda_runtime.h>
#include <math.h>

#define FULL 0xffffffffu

// Precomputed cos/sin of half-angles for the 4 entangler weight sets.
// [ci*10 + w] = (cos(w_ci[w]/2), sin(w_ci[w]/2))
__device__ float2 g_cs[40];

__global__ void setup_kernel(const float* __restrict__ wf,
                             const float* __restrict__ wi,
                             const float* __restrict__ wu,
                             const float* __restrict__ wo) {
    int t = threadIdx.x;
    if (t < 40) {
        int ci = t / 10, w = t % 10;
        const float* p = (ci == 0) ? wf : (ci == 1) ? wi : (ci == 2) ? wu : wo;
        float s, c;
        sincosf(0.5f * p[w], &s, &c);
        g_cs[t] = make_float2(c, s);
    }
}

// ---------------------------------------------------------------------------
// One warp per batch row. 1024 complex amps -> 32 complex per lane.
// Amp index k: bits [9:5] = lane id, bits [4:0] = local register index.
// Wire w <-> bit position p = 9 - w (PennyLane MSB-first).
//
// The trailing CNOT ring is folded into the measurement: it is a GF(2)-linear
// permutation sigma, and <Z_w> = sum_k (-1)^{parity(k & M_w)} p[k] with
// M_w = {0x1FF,0x300,0x380,0x3C0,0x3E0,0x3F0,0x3F8,0x3FC,0x3FE,0x3FF}.
// Lane-mask Lm = M>>5, local-mask lm = M&31:
//   w : 0    1  2  3  4  5  6  7  8  9
//   Lm: 15  24 28 30 31 31 31 31 31 31
//   lm: 31   0  0  0  0 16 24 28 30 31
// Local sums needed: masks {0(S),16,24,28,30,31(A)}.  Lane reductions: full
// 5-stage Hadamard per vector; wire w reads (vector, lane) per table above.
// ---------------------------------------------------------------------------

template<bool RY>
__device__ __forceinline__ float circuit(const float (&m)[32],
                                         const float (&rc)[4],
                                         const float (&ic)[4],
                                         int lane, int base) {
    // -------- materialize psi0 = m[k] * (-i)^popc(k) --------
    float re[32], im[32];
#pragma unroll
    for (int i = 0; i < 32; i++) {
        const int t = __popc(i) & 3;      // compile-time per i
        re[i] = m[i] * rc[t];
        im[i] = m[i] * ic[t];
    }

    // -------- rotations on wires 0..4 (lane bits, j = 4-w) --------
#pragma unroll
    for (int w = 0; w < 5; w++) {
        const float2 cs = g_cs[base + w];
        const float c = cs.x, s = cs.y;
        const int j = 4 - w;
        const float se = ((lane >> j) & 1) ? s : -s;   // RY partner sign
#pragma unroll
        for (int i = 0; i < 32; i++) {
            float pre = __shfl_xor_sync(FULL, re[i], 1 << j);
            float pim = __shfl_xor_sync(FULL, im[i], 1 << j);
            if (RY) {
                re[i] = fmaf(c, re[i], se * pre);
                im[i] = fmaf(c, im[i], se * pim);
            } else {                                    // RX
                re[i] = fmaf(c, re[i], s * pim);
                im[i] = fmaf(c, im[i], -s * pre);
            }
        }
    }

    // -------- rotations on wires 5..9 (local bits, b = 9-w) --------
#pragma unroll
    for (int w = 5; w < 10; w++) {
        const float2 cs = g_cs[base + w];
        const float c = cs.x, s = cs.y;
        const int bb = 1 << (9 - w);
#pragma unroll
        for (int i = 0; i < 32; i++) {
            if (i & bb) continue;
            const int i1 = i | bb;
            float r0 = re[i], q0 = im[i], r1 = re[i1], q1 = im[i1];
            if (RY) {
                re[i]  = c * r0 - s * r1;  im[i]  = c * q0 - s * q1;
                re[i1] = s * r0 + c * r1;  im[i1] = s * q0 + c * q1;
            } else {
                re[i]  = c * r0 + s * q1;  im[i]  = c * q0 - s * r1;
                re[i1] = c * r1 + s * q0;  im[i1] = c * q1 - s * r0;
            }
        }
    }

    // -------- probabilities --------
    float p[32];
#pragma unroll
    for (int i = 0; i < 32; i++) p[i] = fmaf(re[i], re[i], im[i] * im[i]);

    // -------- local Walsh tree: masks {0,16,24,28,30,31} --------
    float s4[16], d4[16];
#pragma unroll
    for (int i = 0; i < 16; i++) { s4[i] = p[i] + p[i + 16]; d4[i] = p[i] - p[i + 16]; }
    float s3[8];
#pragma unroll
    for (int i = 0; i < 8; i++) s3[i] = s4[i] + s4[i + 8];
    float S = ((s3[0] + s3[1]) + (s3[2] + s3[3])) + ((s3[4] + s3[5]) + (s3[6] + s3[7]));

    float ds3[8], dd3[8];
#pragma unroll
    for (int i = 0; i < 8; i++) { ds3[i] = d4[i] + d4[i + 8]; dd3[i] = d4[i] - d4[i + 8]; }
    float T16 = ((ds3[0] + ds3[1]) + (ds3[2] + ds3[3])) + ((ds3[4] + ds3[5]) + (ds3[6] + ds3[7]));

    float dds2[4], ddd2[4];
#pragma unroll
    for (int i = 0; i < 4; i++) { dds2[i] = dd3[i] + dd3[i + 4]; ddd2[i] = dd3[i] - dd3[i + 4]; }
    float T24 = (dds2[0] + dds2[1]) + (dds2[2] + dds2[3]);
    float T28 = (ddd2[0] + ddd2[1]) + (ddd2[2] + ddd2[3]);
    float f0 = ddd2[0] - ddd2[2], f1 = ddd2[1] - ddd2[3];
    float T30 = f0 + f1;
    float A   = f0 - f1;                       // local mask 31

    // -------- lane Hadamards (5 stages each): lane L gets Walsh_L(v) --------
    float HS = S, HA = A, H16 = T16, H24 = T24, H28 = T28, H30 = T30;
#pragma unroll
    for (int j = 0; j < 5; j++) {
        const float sg = ((lane >> j) & 1) ? -1.0f : 1.0f;
        float t;
        t = __shfl_xor_sync(FULL, HS,  1 << j);  HS  = fmaf(sg, HS,  t);
        t = __shfl_xor_sync(FULL, HA,  1 << j);  HA  = fmaf(sg, HA,  t);
        t = __shfl_xor_sync(FULL, H16, 1 << j);  H16 = fmaf(sg, H16, t);
        t = __shfl_xor_sync(FULL, H24, 1 << j);  H24 = fmaf(sg, H24, t);
        t = __shfl_xor_sync(FULL, H28, 1 << j);  H28 = fmaf(sg, H28, t);
        t = __shfl_xor_sync(FULL, H30, 1 << j);  H30 = fmaf(sg, H30, t);
    }

    // -------- gather: lane w <- (vector, source lane) --------
    const int srcS = (lane == 1) ? 24 : (lane == 2) ? 28 : (lane == 3) ? 30 : 31;
    const int srcA = (lane == 0) ? 15 : 31;
    float gS  = __shfl_sync(FULL, HS,  srcS);
    float gA  = __shfl_sync(FULL, HA,  srcA);
    float g16 = __shfl_sync(FULL, H16, 31);
    float g24 = __shfl_sync(FULL, H24, 31);
    float g28 = __shfl_sync(FULL, H28, 31);
    float g30 = __shfl_sync(FULL, H30, 31);

    float e = gS;                                     // lanes 1..4
    if (lane == 0) e = gA;
    else if (lane == 5) e = g16;
    else if (lane == 6) e = g24;
    else if (lane == 7) e = g28;
    else if (lane == 8) e = g30;
    else if (lane == 9) e = gA;
    return e;
}

__global__ void __launch_bounds__(128)
qlstm_kernel(const float* __restrict__ x, const float* __restrict__ W,
             const float* __restrict__ b, float* __restrict__ out) {
    const int warp = (blockIdx.x * blockDim.x + threadIdx.x) >> 5;
    const int lane = threadIdx.x & 31;

    // ---------------- h = x[warp] @ W^T + b (butterfly-reduced) --------------
    const float4 xv = reinterpret_cast<const float4*>(x + (size_t)warp * 128)[lane];
    float h[10];
#pragma unroll
    for (int o = 0; o < 10; o++) {
        const float4 wv = reinterpret_cast<const float4*>(W + o * 128)[lane];
        float acc = xv.x * wv.x + xv.y * wv.y + xv.z * wv.z + xv.w * wv.w;
#pragma unroll
        for (int s = 16; s; s >>= 1) acc += __shfl_xor_sync(FULL, acc, s);
        h[o] = acc + __ldg(b + o);
    }

    // Per-lane angle: lane q computes sincos(h_q/2); broadcast all 10.
    float my_h = h[0];
#pragma unroll
    for (int o = 1; o < 10; o++)
        if (lane == o) my_h = h[o];
    float msn, mcs;
    sincosf(0.5f * my_h, &msn, &mcs);
    float cw[10], sw[10];
#pragma unroll
    for (int w = 0; w < 10; w++) {
        cw[w] = __shfl_sync(FULL, mcs, w);
        sw[w] = __shfl_sync(FULL, msn, w);
    }

    // ------------- product-state magnitudes m[k] (real) -------------
    // lane bit j -> amp bit 5+j -> wire 4-j ; local bit j -> amp bit j -> wire 9-j
    float prefix = 1.0f;
#pragma unroll
    for (int j = 0; j < 5; j++)
        prefix *= ((lane >> j) & 1) ? sw[4 - j] : cw[4 - j];

    float m[32];
    m[0] = prefix;
#pragma unroll
    for (int j = 0; j < 5; j++) {
        const int wq = 9 - j;
#pragma unroll
        for (int i = 0; i < (1 << j); i++) {
            m[i | (1 << j)] = m[i] * sw[wq];
            m[i]            = m[i] * cw[wq];
        }
    }

    // Phase (-i)^popc(k): class tables by popc(local)&3, offset by popc(lane).
    const int pb = __popc(lane) & 3;
    float rc[4], ic[4];
#pragma unroll
    for (int t = 0; t < 4; t++) {
        int ph = (pb + t) & 3;
        rc[t] = (ph == 0) ? 1.0f : (ph == 2) ? -1.0f : 0.0f;
        ic[t] = (ph == 1) ? -1.0f : (ph == 3) ? 1.0f : 0.0f;
    }

    // ---------------- 4 circuits: one RX body (looped) + one RY body --------
    float e0 = 0.f, e2 = 0.f, e3 = 0.f;
#pragma unroll 1
    for (int t = 0; t < 3; t++) {
        const int base = (t == 0) ? 0 : (t == 1) ? 20 : 30;
        float r = circuit<false>(m, rc, ic, lane, base);
        if (t == 0) e0 = r; else if (t == 1) e2 = r; else e3 = r;
    }
    float e1 = circuit<true>(m, rc, ic, lane, 10);

    // ---------------- LSTM combine (lanes 0..9 hold their wire) -------------
    if (lane < 10) {
        float ing = 1.0f / (1.0f + expf(-e0));   // sigmoid(vqc RX w_forget)
        float fg  = 1.0f / (1.0f + expf(-e1));   // sigmoid(vqc RY w_input)
        float cg  = tanhf(e2);                   // tanh(vqc RX w_update)
        float og  = 1.0f / (1.0f + expf(-e3));   // sigmoid(vqc RX w_output)
        float nh  = my_h * fg + ing * cg;
        out[warp * 10 + lane] = og * tanhf(nh);
    }
}

extern "C" void kernel_launch(void* const* d_in, const int* in_sizes, int n_in,
                              void* d_out, int out_size) {
    const float* x  = (const float*)d_in[0];
    const float* W  = (const float*)d_in[1];
    const float* b  = (const float*)d_in[2];
    const float* wf = (const float*)d_in[3];
    const float* wi = (const float*)d_in[4];
    const float* wu = (const float*)d_in[5];
    const float* wo = (const float*)d_in[6];
    float* out = (float*)d_out;

    setup_kernel<<<1, 64>>>(wf, wi, wu, wo);
    qlstm_kernel<<<4096, 128>>>(x, W, b, out);
}

// round 3
// speedup vs baseline: 15.2842x; 12.1705x over previous
#include <cuda_runtime.h>
#include <math.h>

#define FULL 0xffffffffu

// ---------------------------------------------------------------------------
// Closed form: after folding the trailing CNOT ring into the PauliZ
// measurements (GF(2)-linear masks, verified in earlier rounds), the state at
// measurement time is a product state, so
//   <Z_w> = prod_{q in M_w} z_q,
//   M_w = {0..w} for w>=1,  M_0 = {1..9}   (wire-index sets)
// with per-qubit single-axis closed forms:
//   RX(theta) after RX(h):  z = cos(h + theta)
//   RY(theta) after RX(h):  z = cos(theta) * cos(h)
// Whole kernel = skinny GEMM (h = x W^T + b) + 5 cos + 4 lane-prefix products
// + LSTM combine. One warp per batch row.
// ---------------------------------------------------------------------------
__global__ void __launch_bounds__(256)
qlstm_kernel(const float* __restrict__ x, const float* __restrict__ W,
             const float* __restrict__ b,
             const float* __restrict__ wf, const float* __restrict__ wi,
             const float* __restrict__ wu, const float* __restrict__ wo,
             float* __restrict__ out) {
    const int warp = (blockIdx.x * blockDim.x + threadIdx.x) >> 5;
    const int lane = threadIdx.x & 31;

    // -------- h = x[row] @ W^T + b : coalesced float4 + butterfly ----------
    const float4 xv = reinterpret_cast<const float4*>(x + (size_t)warp * 128)[lane];
    float h[10];
#pragma unroll
    for (int o = 0; o < 10; o++) {
        const float4 wv = reinterpret_cast<const float4*>(W + o * 128)[lane];
        float acc = xv.x * wv.x + xv.y * wv.y + xv.z * wv.z + xv.w * wv.w;
#pragma unroll
        for (int s = 16; s; s >>= 1) acc += __shfl_xor_sync(FULL, acc, s);
        h[o] = acc;
    }
    float my_h = h[0];
#pragma unroll
    for (int o = 1; o < 10; o++)
        if (lane == o) my_h = h[o];

    // -------- per-wire single-qubit <Z> values (lanes 0..9) ----------------
    float zf = 1.0f, zi = 1.0f, zu = 1.0f, zo = 1.0f;
    if (lane < 10) {
        my_h += __ldg(b + lane);
        const float ch = cosf(my_h);
        zf = cosf(my_h + __ldg(wf + lane));      // RX circuit (w_forget)
        zi = cosf(__ldg(wi + lane)) * ch;        // RY circuit (w_input)
        zu = cosf(my_h + __ldg(wu + lane));      // RX circuit (w_update)
        zo = cosf(my_h + __ldg(wo + lane));      // RX circuit (w_output)
    }

    // -------- inclusive prefix products with lane-0 masked to 1 ------------
    // P_w = prod_{q=1..w} z_q ; then E_w = z_0 * P_w (w>=1), E_0 = P_9.
    float pf = (lane == 0) ? 1.0f : zf;
    float pi = (lane == 0) ? 1.0f : zi;
    float pu = (lane == 0) ? 1.0f : zu;
    float po = (lane == 0) ? 1.0f : zo;
#pragma unroll
    for (int d = 1; d < 16; d <<= 1) {
        float t;
        t = __shfl_up_sync(FULL, pf, d); if (lane >= d) pf *= t;
        t = __shfl_up_sync(FULL, pi, d); if (lane >= d) pi *= t;
        t = __shfl_up_sync(FULL, pu, d); if (lane >= d) pu *= t;
        t = __shfl_up_sync(FULL, po, d); if (lane >= d) po *= t;
    }

    const float z0f = __shfl_sync(FULL, zf, 0), q9f = __shfl_sync(FULL, pf, 9);
    const float z0i = __shfl_sync(FULL, zi, 0), q9i = __shfl_sync(FULL, pi, 9);
    const float z0u = __shfl_sync(FULL, zu, 0), q9u = __shfl_sync(FULL, pu, 9);
    const float z0o = __shfl_sync(FULL, zo, 0), q9o = __shfl_sync(FULL, po, 9);

    if (lane < 10) {
        const float e0 = (lane == 0) ? q9f : z0f * pf;   // vqc(w_forget, RX)
        const float e1 = (lane == 0) ? q9i : z0i * pi;   // vqc(w_input,  RY)
        const float e2 = (lane == 0) ? q9u : z0u * pu;   // vqc(w_update, RX)
        const float e3 = (lane == 0) ? q9o : z0o * po;   // vqc(w_output, RX)

        const float ing = 1.0f / (1.0f + expf(-e0));
        const float fg  = 1.0f / (1.0f + expf(-e1));
        const float cg  = tanhf(e2);
        const float og  = 1.0f / (1.0f + expf(-e3));
        const float nh  = my_h * fg + ing * cg;
        out[warp * 10 + lane] = og * tanhf(nh);
    }
}

extern "C" void kernel_launch(void* const* d_in, const int* in_sizes, int n_in,
                              void* d_out, int out_size) {
    const float* x  = (const float*)d_in[0];
    const float* W  = (const float*)d_in[1];
    const float* b  = (const float*)d_in[2];
    const float* wf = (const float*)d_in[3];
    const float* wi = (const float*)d_in[4];
    const float* wu = (const float*)d_in[5];
    const float* wo = (const float*)d_in[6];
    float* out = (float*)d_out;

    // 16384 rows, one warp each: 2048 blocks x 256 threads
    qlstm_kernel<<<2048, 256>>>(x, W, b, wf, wi, wu, wo, out);
}

// round 4
// speedup vs baseline: 22.5466x; 1.4752x over previous
#include <cuda_runtime.h>
#include <math.h>

#define FULL 0xffffffffu

// ---------------------------------------------------------------------------
// Closed form (verified rounds 1-3): fold the trailing CNOT ring into the
// PauliZ masks; the state at measurement is then a product state, so
//   <Z_w> = prod_{q in M_w} z_q,  M_w = {0..w} (w>=1), M_0 = {1..9}
//   RX-circuit: z = cos(h + theta) ; RY-circuit: z = cos(theta)*cos(h)
//
// Layout: 4 threads per row ("quad"), 8 rows per warp, 64 rows per 256-block.
//  - GEMM: thread computes 10 partial dots over its 32-column quarter
//    (x via coalesced interleaved float4, W from smem), quad xor-reduce.
//  - Thread q owns wires {3q,3q+1,3q+2} (q=3: wire 9 only): trig + expvals.
//  - Prefix products across the quad via width-4 segmented scans.
// ---------------------------------------------------------------------------
__global__ void __launch_bounds__(256)
qlstm_kernel(const float* __restrict__ x, const float* __restrict__ W,
             const float* __restrict__ b,
             const float* __restrict__ wf, const float* __restrict__ wi,
             const float* __restrict__ wu, const float* __restrict__ wo,
             float* __restrict__ out) {
    __shared__ float4 Ws[320];                 // W[o][f4]: [o*32 + f]
    __shared__ float2 s_f[10], s_u[10], s_o[10];
    __shared__ float  s_i[10];

    const int tid = threadIdx.x;

    // ---- per-block setup: W -> smem, accurate sincos of weight angles ----
#pragma unroll
    for (int idx = tid; idx < 320; idx += 256)
        Ws[idx] = reinterpret_cast<const float4*>(W)[idx];
    if (tid < 40) {
        const int g = tid / 10, w = tid % 10;
        const float* p = (g == 0) ? wf : (g == 1) ? wi : (g == 2) ? wu : wo;
        float s, c;
        sincosf(p[w], &s, &c);
        if (g == 0)      s_f[w] = make_float2(c, s);
        else if (g == 1) s_i[w] = c;
        else if (g == 2) s_u[w] = make_float2(c, s);
        else             s_o[w] = make_float2(c, s);
    }
    __syncthreads();

    const int lane = tid & 31;
    const int q = lane & 3;                    // quarter within row
    const int row = (blockIdx.x * 256 + tid) >> 2;

    // ---- GEMM: h = x[row] @ W^T (quarter-columns per thread) ----
    const float4* x4 = reinterpret_cast<const float4*>(x) + (size_t)row * 32;
    float4 xv[8];
#pragma unroll
    for (int i = 0; i < 8; i++) xv[i] = x4[i * 4 + q];

    float acc[10];
#pragma unroll
    for (int o = 0; o < 10; o++) acc[o] = 0.0f;
#pragma unroll
    for (int i = 0; i < 8; i++) {
#pragma unroll
        for (int o = 0; o < 10; o++) {
            const float4 wv = Ws[o * 32 + i * 4 + q];
            acc[o] = fmaf(xv[i].x, wv.x,
                     fmaf(xv[i].y, wv.y,
                     fmaf(xv[i].z, wv.z,
                     fmaf(xv[i].w, wv.w, acc[o]))));
        }
    }
    // quad reduction (xor 1, xor 2 stay within the quad)
#pragma unroll
    for (int o = 0; o < 10; o++) {
        acc[o] += __shfl_xor_sync(FULL, acc[o], 1);
        acc[o] += __shfl_xor_sync(FULL, acc[o], 2);
    }

    // ---- owned wires: w = 3q + j (q==3 owns only wire 9) ----
    const int nw = (q < 3) ? 3 : 1;
    const int w0 = 3 * q;

    float myh[3], zf[3], zi[3], zu[3], zo[3];
#pragma unroll
    for (int j = 0; j < 3; j++) {
        // static-index select of acc[3q+j] (avoid dynamic register indexing)
        float hv = acc[j];
        if (q == 1) hv = acc[3 + j];
        if (q == 2) hv = acc[6 + j];
        if (q == 3) hv = (j == 0) ? acc[9] : 0.0f;

        if (j < nw) {
            const int w = w0 + j;
            const float h = hv + __ldg(b + w);
            myh[j] = h;
            float sh, ch;
            __sincosf(h, &sh, &ch);
            const float2 cf = s_f[w], cu = s_u[w], co = s_o[w];
            zf[j] = ch * cf.x - sh * cf.y;     // RX: cos(h + wf)
            zi[j] = s_i[w] * ch;               // RY: cos(wi) * cos(h)
            zu[j] = ch * cu.x - sh * cu.y;
            zo[j] = ch * co.x - sh * co.y;
        } else {
            myh[j] = 0.0f;
            zf[j] = zi[j] = zu[j] = zo[j] = 1.0f;  // neutral
        }
    }

    // ---- per-circuit quad prefix products -> E[3] per circuit ----
    // locals: l1 = z0l, l2 = z0l*z1l, l3 = l2*z2l ; T = l3
    // forward scan -> exclusive prefix C; suffix scan -> R0 = T1*T2*T3 (for wire 0)
    float Ef[3], Ei[3], Eu[3], Eo[3];
#pragma unroll
    for (int c = 0; c < 4; c++) {
        const float* z = (c == 0) ? zf : (c == 1) ? zi : (c == 2) ? zu : zo;
        const float l1 = z[0], l2 = l1 * z[1], l3 = l2 * z[2];

        float v = l3, t;
        t = __shfl_up_sync(FULL, v, 1, 4); if (q >= 1) v *= t;
        t = __shfl_up_sync(FULL, v, 2, 4); if (q >= 2) v *= t;
        float C = __shfl_up_sync(FULL, v, 1, 4); if (q == 0) C = 1.0f;

        float s = l3;
        t = __shfl_down_sync(FULL, s, 1, 4); if (q <= 2) s *= t;
        t = __shfl_down_sync(FULL, s, 2, 4); if (q <= 1) s *= t;
        const float R0 = __shfl_sync(FULL, s, 1, 4);   // suffix at quad-lane 1

        float E0 = C * l1;                              // inclusive prefix P_w
        if (q == 0) E0 = z[1] * z[2] * R0;              // wire 0: z1..z9
        const float E1 = C * l2, E2 = C * l3;

        if (c == 0)      { Ef[0] = E0; Ef[1] = E1; Ef[2] = E2; }
        else if (c == 1) { Ei[0] = E0; Ei[1] = E1; Ei[2] = E2; }
        else if (c == 2) { Eu[0] = E0; Eu[1] = E1; Eu[2] = E2; }
        else             { Eo[0] = E0; Eo[1] = E1; Eo[2] = E2; }
    }

    // ---- LSTM epilogue per owned wire ----
#pragma unroll
    for (int j = 0; j < 3; j++) {
        if (j < nw) {
            const float ing = __fdividef(1.0f, 1.0f + __expf(-Ef[j]));
            const float fg  = __fdividef(1.0f, 1.0f + __expf(-Ei[j]));
            const float cg  = __fdividef(2.0f, 1.0f + __expf(-2.0f * Eu[j])) - 1.0f;
            const float og  = __fdividef(1.0f, 1.0f + __expf(-Eo[j]));
            const float nh  = fmaf(myh[j], fg, ing * cg);
            const float th  = __fdividef(2.0f, 1.0f + __expf(-2.0f * nh)) - 1.0f;
            out[row * 10 + w0 + j] = og * th;
        }
    }
}

extern "C" void kernel_launch(void* const* d_in, const int* in_sizes, int n_in,
                              void* d_out, int out_size) {
    const float* x  = (const float*)d_in[0];
    const float* W  = (const float*)d_in[1];
    const float* b  = (const float*)d_in[2];
    const float* wf = (const float*)d_in[3];
    const float* wi = (const float*)d_in[4];
    const float* wu = (const float*)d_in[5];
    const float* wo = (const float*)d_in[6];
    float* out = (float*)d_out;

    // 16384 rows x 4 threads = 65536 threads; 256 per block -> 256 blocks
    qlstm_kernel<<<256, 256>>>(x, W, b, wf, wi, wu, wo, out);
}